// round 9
// baseline (speedup 1.0000x reference)
#include <cuda_runtime.h>
#include <cstdint>

#define BB 8
#define CC 512
#define DD 64
#define NN 16384
#define PARAM 10.0f
#define EPS 1e-6f

__device__ float    g_Q[BB*DD*NN];       // phi(Q) f32 [b][m][n]
__device__ uint32_t g_Ktp[BB*(NN/2)*DD]; // phi(K) bf16x2 [b][n/2][m] (pair along n)
__device__ float    g_Ksum[BB*DD];
__device__ float    g_KXT[BB*CC*DD];     // (phiK @ x^T)^T f32 [b][c][m]
__device__ float    g_KVT[BB*CC*DD];     // KV^T (no bias) f32 [b][c][m]

__device__ __forceinline__ float fmap(float t) {
    return t > 0.f ? fmaf(PARAM, t, 1.f) : __expf(PARAM * t);
}
// pack (lo,hi) floats -> bf16x2 (lo = first k of the pair)
__device__ __forceinline__ uint32_t bfp(float lo, float hi) {
    uint32_t r; asm("cvt.rn.bf16x2.f32 %0, %1, %2;" : "=r"(r) : "f"(hi), "f"(lo));
    return r;
}
#define MMA16(d, a, b0, b1) \
    asm volatile("mma.sync.aligned.m16n8k16.row.col.f32.bf16.bf16.f32 " \
        "{%0,%1,%2,%3}, {%4,%5,%6,%7}, {%8,%9}, {%0,%1,%2,%3};" \
        : "+f"((d)[0]), "+f"((d)[1]), "+f"((d)[2]), "+f"((d)[3]) \
        : "r"((a)[0]), "r"((a)[1]), "r"((a)[2]), "r"((a)[3]), "r"(b0), "r"(b1))

// ---------------------------------------------------------------------------
__global__ void k_zero() {
    int i = blockIdx.x*blockDim.x + threadIdx.x;
    if (i < BB*CC*DD) { g_KXT[i] = 0.f; g_KVT[i] = 0.f; }
    if (i < BB*DD) g_Ksum[i] = 0.f;
}

// ---------------------------------------------------------------------------
// k_qk: [Wq;Wk](128x512) @ x_tile(512 x 128n), bf16 m16n8k16.
// Smem in fragment layout. Epilogue: Q->f32 g_Q, K->packed g_Ktp + Ksum.
// ---------------------------------------------------------------------------
__global__ __launch_bounds__(256) void k_qk(const float* __restrict__ x,
        const float* __restrict__ Wq, const float* __restrict__ bq,
        const float* __restrict__ Wk, const float* __restrict__ bk) {
    __shared__ uint32_t As[2048];   // [mt8][ks2][gr8][qt4][reg4]
    __shared__ uint32_t Bs[2048];   // [nt16][ks2][gr8][qt4][reg2]
    const int tid = threadIdx.x, w = tid>>5, lane = tid&31;
    const int gr = lane>>2, qt = lane&3;
    const int b = blockIdx.y, n0 = blockIdx.x*128;
    const int M0 = (w>>1)*32, N0 = (w&1)*64;
    const float* xb = x + (size_t)b*CC*NN;

    float4 pA[4], pB0[2], pB1[2];
    #pragma unroll
    for (int i = 0; i < 4; i++) {
        int id = tid + i*256, r = id>>3, c4 = id&7;
        const float* Wr = r < 64 ? Wq + r*CC : Wk + (size_t)(r-64)*CC;
        pA[i] = *(const float4*)(Wr + c4*4);
    }
    #pragma unroll
    for (int it = 0; it < 2; it++) {
        int n4 = tid&31, kp = (tid>>5) + it*8;
        pB0[it] = *(const float4*)(xb + (size_t)(2*kp  )*NN + n0 + n4*4);
        pB1[it] = *(const float4*)(xb + (size_t)(2*kp+1)*NN + n0 + n4*4);
    }
    float acc[2][8][4];
    #pragma unroll
    for (int mt = 0; mt < 2; mt++)
        #pragma unroll
        for (int nt = 0; nt < 8; nt++)
            #pragma unroll
            for (int i = 0; i < 4; i++) acc[mt][nt][i] = 0.f;

    for (int ci = 0; ci < 16; ci++) {
        #pragma unroll
        for (int i = 0; i < 4; i++) {      // A: pairs along k(c)
            int id = tid + i*256, r = id>>3, c4 = id&7;
            int mt = r>>4, h = (r>>3)&1, g = r&7;
            int ks = c4>>2, pq = (2*c4)&7, q0 = pq&3, reg = h + 2*(pq>>2);
            int base = ((mt*2+ks)*8+g)*4;
            As[(base+q0  )*4 + reg] = bfp(pA[i].x, pA[i].y);
            As[(base+q0+1)*4 + reg] = bfp(pA[i].z, pA[i].w);
        }
        #pragma unroll
        for (int it = 0; it < 2; it++) {   // B: pairs along k from two rows
            int n4 = tid&31, kp = (tid>>5) + it*8;
            int ks = kp>>3, pq = kp&7, qb = pq&3, rb = pq>>2;
            float a0[4] = {pB0[it].x, pB0[it].y, pB0[it].z, pB0[it].w};
            float a1[4] = {pB1[it].x, pB1[it].y, pB1[it].z, pB1[it].w};
            #pragma unroll
            for (int j = 0; j < 4; j++) {
                int n = n4*4 + j, nt = n>>3, g = n&7;
                Bs[(((nt*2+ks)*8+g)*4+qb)*2 + rb] = bfp(a0[j], a1[j]);
            }
        }
        __syncthreads();
        if (ci < 15) {
            int kc = (ci+1)*32;
            #pragma unroll
            for (int i = 0; i < 4; i++) {
                int id = tid + i*256, r = id>>3, c4 = id&7;
                const float* Wr = r < 64 ? Wq + r*CC : Wk + (size_t)(r-64)*CC;
                pA[i] = *(const float4*)(Wr + kc + c4*4);
            }
            #pragma unroll
            for (int it = 0; it < 2; it++) {
                int n4 = tid&31, kp = (tid>>5) + it*8;
                pB0[it] = *(const float4*)(xb + (size_t)(kc+2*kp  )*NN + n0 + n4*4);
                pB1[it] = *(const float4*)(xb + (size_t)(kc+2*kp+1)*NN + n0 + n4*4);
            }
        }
        #pragma unroll
        for (int ks = 0; ks < 2; ks++) {
            uint4 af[2];
            uint2 bf[8];
            #pragma unroll
            for (int mt = 0; mt < 2; mt++)
                af[mt] = *(uint4*)&As[((((w>>1)*2+mt)*2+ks)*8+gr)*16 + qt*4];
            #pragma unroll
            for (int nt = 0; nt < 8; nt++)
                bf[nt] = *(uint2*)&Bs[((((N0>>3)+nt)*2+ks)*8+gr)*8 + qt*2];
            #pragma unroll
            for (int mt = 0; mt < 2; mt++) {
                uint32_t a[4] = {af[mt].x, af[mt].y, af[mt].z, af[mt].w};
                #pragma unroll
                for (int nt = 0; nt < 8; nt++)
                    MMA16(acc[mt][nt], a, bf[nt].x, bf[nt].y);
            }
        }
        __syncthreads();
    }

    #pragma unroll
    for (int mt = 0; mt < 2; mt++)
        #pragma unroll
        for (int h = 0; h < 2; h++) {
            const int m = M0 + 16*mt + 8*h + gr;
            const float bias = m < 64 ? __ldg(bq + m) : __ldg(bk + m - 64);
            float vv[8][2], ks = 0.f;
            #pragma unroll
            for (int nt = 0; nt < 8; nt++) {
                vv[nt][0] = fmap(acc[mt][nt][2*h]   + bias);
                vv[nt][1] = fmap(acc[mt][nt][2*h+1] + bias);
                ks += vv[nt][0] + vv[nt][1];
            }
            if (m < 64) {
                float* dst = g_Q + ((size_t)b*DD + m)*NN + n0 + N0;
                #pragma unroll
                for (int nt = 0; nt < 8; nt++)
                    *(float2*)(dst + 8*nt + 2*qt) = make_float2(vv[nt][0], vv[nt][1]);
            } else {
                const int mm = m - 64;
                #pragma unroll
                for (int nt = 0; nt < 8; nt++) {
                    int np = ((n0 + N0)>>1) + 4*nt + qt;
                    g_Ktp[((size_t)b*(NN/2) + np)*DD + mm] = bfp(vv[nt][0], vv[nt][1]);
                }
                ks += __shfl_xor_sync(0xffffffffu, ks, 1);
                ks += __shfl_xor_sync(0xffffffffu, ks, 2);
                if (qt == 0) atomicAdd(&g_Ksum[b*DD + mm], ks);
            }
        }
}

// ---------------------------------------------------------------------------
// k_kx: KXT[128c][64m] += x_tile @ phiK^T, bf16. A=x (pairs along n natural),
// B=g_Ktp pre-packed. Split-K=16, L2 atomics.
// ---------------------------------------------------------------------------
__global__ __launch_bounds__(256) void k_kx(const float* __restrict__ x) {
    __shared__ uint32_t As[2048];   // [ct8][ks2][gr8][qt4][reg4]
    __shared__ uint32_t Bs[1024];   // [mt8][ks2][gr8][qt4][reg2]
    const int tid = threadIdx.x, w = tid>>5, lane = tid&31;
    const int gr = lane>>2, qt = lane&3;
    const int c0 = blockIdx.x*128, b = blockIdx.z;
    const int nbase = blockIdx.y*(NN/16);
    const int M0 = (w>>1)*32, N0 = (w&1)*32;

    float4 pA[4];
    uint4 pB;
    #pragma unroll
    for (int i = 0; i < 4; i++) {
        int id = tid + i*256, r = id>>3, c4 = id&7;
        pA[i] = *(const float4*)(x + ((size_t)(b*CC + c0 + r))*NN + nbase + c4*4);
    }
    {
        int npl = tid>>4, m4 = tid&15;
        pB = *(const uint4*)&g_Ktp[((size_t)b*(NN/2) + (nbase>>1) + npl)*DD + m4*4];
    }
    float acc[2][4][4];
    #pragma unroll
    for (int mt = 0; mt < 2; mt++)
        #pragma unroll
        for (int nt = 0; nt < 4; nt++)
            #pragma unroll
            for (int i = 0; i < 4; i++) acc[mt][nt][i] = 0.f;

    for (int ci = 0; ci < 32; ci++) {
        #pragma unroll
        for (int i = 0; i < 4; i++) {
            int id = tid + i*256, r = id>>3, c4 = id&7;
            int ct = r>>4, h = (r>>3)&1, g = r&7;
            int ks = c4>>2, pq = (2*c4)&7, q0 = pq&3, reg = h + 2*(pq>>2);
            int base = ((ct*2+ks)*8+g)*4;
            As[(base+q0  )*4 + reg] = bfp(pA[i].x, pA[i].y);
            As[(base+q0+1)*4 + reg] = bfp(pA[i].z, pA[i].w);
        }
        {
            int npl = tid>>4, m4 = tid&15;
            int ks = npl>>3, pq = npl&7, qb = pq&3, rb = pq>>2;
            uint32_t u[4] = {pB.x, pB.y, pB.z, pB.w};
            #pragma unroll
            for (int j = 0; j < 4; j++) {
                int m = m4*4 + j, mt = m>>3, g = m&7;
                Bs[(((mt*2+ks)*8+g)*4+qb)*2 + rb] = u[j];
            }
        }
        __syncthreads();
        if (ci < 31) {
            int kn = nbase + (ci+1)*32;
            #pragma unroll
            for (int i = 0; i < 4; i++) {
                int id = tid + i*256, r = id>>3, c4 = id&7;
                pA[i] = *(const float4*)(x + ((size_t)(b*CC + c0 + r))*NN + kn + c4*4);
            }
            int npl = tid>>4, m4 = tid&15;
            pB = *(const uint4*)&g_Ktp[((size_t)b*(NN/2) + (kn>>1) + npl)*DD + m4*4];
        }
        #pragma unroll
        for (int ks = 0; ks < 2; ks++) {
            uint4 af[2];
            uint2 bf[4];
            #pragma unroll
            for (int mt = 0; mt < 2; mt++)
                af[mt] = *(uint4*)&As[((((w>>1)*2+mt)*2+ks)*8+gr)*16 + qt*4];
            #pragma unroll
            for (int nt = 0; nt < 4; nt++)
                bf[nt] = *(uint2*)&Bs[((((N0>>3)+nt)*2+ks)*8+gr)*8 + qt*2];
            #pragma unroll
            for (int mt = 0; mt < 2; mt++) {
                uint32_t a[4] = {af[mt].x, af[mt].y, af[mt].z, af[mt].w};
                #pragma unroll
                for (int nt = 0; nt < 4; nt++)
                    MMA16(acc[mt][nt], a, bf[nt].x, bf[nt].y);
            }
        }
        __syncthreads();
    }
    #pragma unroll
    for (int mt = 0; mt < 2; mt++)
        #pragma unroll
        for (int h = 0; h < 2; h++) {
            int c = c0 + M0 + 16*mt + 8*h + gr;
            #pragma unroll
            for (int nt = 0; nt < 4; nt++) {
                int m = N0 + 8*nt + 2*qt;
                float* d = g_KXT + ((size_t)b*CC + c)*DD + m;
                atomicAdd(d,     acc[mt][nt][2*h]);
                atomicAdd(d + 1, acc[mt][nt][2*h+1]);
            }
        }
}

// ---------------------------------------------------------------------------
// k_kv (SIMT f32, split-K=4): KVT[c][m] += sum_{c'} Wv[c][c'] * KXT[c'][m]
// ---------------------------------------------------------------------------
__global__ __launch_bounds__(256) void k_kv(const float* __restrict__ Wv) {
    __shared__ float Ws[64*36];
    __shared__ float Xs[32*68];
    const int c0 = blockIdx.x*64, sp = blockIdx.y, b = blockIdx.z;
    const int tid = threadIdx.x, tx = tid&15, ty = tid>>4;

    float acc[4][4] = {};
    for (int kk = 0; kk < 4; kk++) {
        const int cp0 = sp*128 + kk*32;
        #pragma unroll
        for (int i = 0; i < 2; i++) {
            int id = tid + i*256, r = id>>3, q4 = id&7;
            *(float4*)&Ws[r*36 + q4*4] =
                *(const float4*)(Wv + (size_t)(c0 + r)*CC + cp0 + q4*4);
        }
        #pragma unroll
        for (int i = 0; i < 2; i++) {
            int id = tid + i*256, r = id>>4, m4 = id&15;
            *(float4*)&Xs[r*68 + m4*4] =
                *(const float4*)(g_KXT + ((size_t)(b*CC) + cp0 + r)*DD + m4*4);
        }
        __syncthreads();
        #pragma unroll
        for (int k = 0; k < 32; k++) {
            float a[4], bb[4];
            #pragma unroll
            for (int i = 0; i < 4; i++) a[i] = Ws[(ty*4+i)*36 + k];
            #pragma unroll
            for (int j = 0; j < 4; j++) bb[j] = Xs[k*68 + tx*4 + j];
            #pragma unroll
            for (int i = 0; i < 4; i++)
                #pragma unroll
                for (int j = 0; j < 4; j++)
                    acc[i][j] = fmaf(a[i], bb[j], acc[i][j]);
        }
        __syncthreads();
    }
    #pragma unroll
    for (int i = 0; i < 4; i++)
        #pragma unroll
        for (int j = 0; j < 4; j++)
            atomicAdd(&g_KVT[((size_t)b*CC + c0 + ty*4+i)*DD + tx*4 + j], acc[i][j]);
}

// ---------------------------------------------------------------------------
// k_out: bf16. One block owns 64-n stripe; B=phiQ loaded once (pairs along m
// from two rows); A=(KVT+bv*Ksum) per c-chunk (pairs along m natural).
// Fused den (from packed Bs) + residual.
// ---------------------------------------------------------------------------
__global__ __launch_bounds__(256) void k_out(const float* __restrict__ x,
        const float* __restrict__ bv, const float* __restrict__ gamma,
        float* __restrict__ out) {
    __shared__ uint32_t As[2048];   // [ct4][ks4][gr8][qt4][reg4]
    __shared__ uint32_t Bs[2048];   // [nt8][ks4][gr8][qt4][reg2]
    __shared__ float dens[64], kss[64];
    const int tid = threadIdx.x, w = tid>>5, lane = tid&31;
    const int gr = lane>>2, qt = lane&3;
    const int n0 = blockIdx.x*64, b = blockIdx.y;
    const int M0 = (w>>1)*16, N0 = (w&1)*32;
    const int ct = w>>1;

    if (tid < 64) kss[tid] = g_Ksum[b*DD + tid];
    #pragma unroll
    for (int it = 0; it < 2; it++) {   // B = phiQ, pairs along m from 2 rows
        int id = tid + it*256, n4 = id&15, mp = id>>4;
        float4 v0 = *(const float4*)(g_Q + ((size_t)b*DD + 2*mp  )*NN + n0 + n4*4);
        float4 v1 = *(const float4*)(g_Q + ((size_t)b*DD + 2*mp+1)*NN + n0 + n4*4);
        int ks = mp>>3, pq = mp&7, qb = pq&3, rb = pq>>2;
        float a0[4] = {v0.x, v0.y, v0.z, v0.w};
        float a1[4] = {v1.x, v1.y, v1.z, v1.w};
        #pragma unroll
        for (int j = 0; j < 4; j++) {
            int n = n4*4 + j, nt = n>>3, g = n&7;
            Bs[(((nt*4+ks)*8+g)*4+qb)*2 + rb] = bfp(a0[j], a1[j]);
        }
    }
    __syncthreads();
    if (tid < 64) {                    // den from packed fragments
        int nt = tid>>3, g = tid&7;
        float d = 0.f;
        #pragma unroll
        for (int ks = 0; ks < 4; ks++)
            #pragma unroll
            for (int q = 0; q < 4; q++)
                #pragma unroll
                for (int rg = 0; rg < 2; rg++) {
                    uint32_t u = Bs[(((nt*4+ks)*8+g)*4+q)*2 + rg];
                    int m0 = ks*16 + 2*(q + 4*rg);
                    float lo = __uint_as_float(u << 16);
                    float hi = __uint_as_float(u & 0xffff0000u);
                    d += lo*(kss[m0] + EPS) + hi*(kss[m0+1] + EPS);
                }
        dens[tid] = d;
    }
    const float gm = gamma[0];

    for (int c0 = 0; c0 < CC; c0 += 64) {
        #pragma unroll
        for (int i = 0; i < 4; i++) {  // A = KVT + bv*Ksum, pairs along m
            int id = tid + i*256, r = id>>4, m4 = id&15;
            float4 v = *(const float4*)(g_KVT + ((size_t)b*CC + c0 + r)*DD + m4*4);
            float4 k4 = *(const float4*)(g_Ksum + b*DD + m4*4);
            float bvc = __ldg(bv + c0 + r);
            v.x = fmaf(bvc, k4.x, v.x); v.y = fmaf(bvc, k4.y, v.y);
            v.z = fmaf(bvc, k4.z, v.z); v.w = fmaf(bvc, k4.w, v.w);
            int cti = r>>4, h = (r>>3)&1, g = r&7;
            int ks = m4>>2, pq = (2*m4)&7, q0 = pq&3, reg = h + 2*(pq>>2);
            int base = ((cti*4+ks)*8+g)*4;
            As[(base+q0  )*4 + reg] = bfp(v.x, v.y);
            As[(base+q0+1)*4 + reg] = bfp(v.z, v.w);
        }
        __syncthreads();

        float acc[4][4];
        #pragma unroll
        for (int nt = 0; nt < 4; nt++)
            #pragma unroll
            for (int i = 0; i < 4; i++) acc[nt][i] = 0.f;
        #pragma unroll
        for (int ks = 0; ks < 4; ks++) {
            uint4 af = *(uint4*)&As[((ct*4+ks)*8+gr)*16 + qt*4];
            uint32_t a[4] = {af.x, af.y, af.z, af.w};
            #pragma unroll
            for (int nt = 0; nt < 4; nt++) {
                uint2 bf = *(uint2*)&Bs[((((N0>>3)+nt)*4+ks)*8+gr)*8 + qt*2];
                MMA16(acc[nt], a, bf.x, bf.y);
            }
        }
        #pragma unroll
        for (int h = 0; h < 2; h++) {
            const int c = c0 + M0 + 8*h + gr;
            #pragma unroll
            for (int nt = 0; nt < 4; nt++) {
                const int nl = N0 + 8*nt + 2*qt;
                const float rn0 = gm / dens[nl], rn1 = gm / dens[nl+1];
                const size_t bi = ((size_t)b*CC + c)*NN + n0 + nl;
                float2 xv = *(const float2*)(x + bi);
                float2 o;
                o.x = fmaf(acc[nt][2*h],   rn0, xv.x);
                o.y = fmaf(acc[nt][2*h+1], rn1, xv.y);
                *(float2*)(out + bi) = o;
            }
        }
        __syncthreads();
    }
}

// ---------------------------------------------------------------------------
extern "C" void kernel_launch(void* const* d_in, const int* in_sizes, int n_in,
                              void* d_out, int out_size) {
    const float* x     = (const float*)d_in[0];
    const float* Wq    = (const float*)d_in[1];
    const float* bq    = (const float*)d_in[2];
    const float* Wk    = (const float*)d_in[3];
    const float* bk    = (const float*)d_in[4];
    const float* Wv    = (const float*)d_in[5];
    const float* bv    = (const float*)d_in[6];
    const float* gamma = (const float*)d_in[7];
    float* out = (float*)d_out;

    k_zero<<<512, 512>>>();
    k_qk  <<<dim3(NN/128, BB), 256>>>(x, Wq, bq, Wk, bk);
    k_kx  <<<dim3(CC/128, 16, BB), 256>>>(x);
    k_kv  <<<dim3(CC/64, 4, BB), 256>>>(Wv);
    k_out <<<dim3(NN/64, BB), 256>>>(x, bv, gamma, out);
}

// round 10
// speedup vs baseline: 1.2672x; 1.2672x over previous
#include <cuda_runtime.h>
#include <cstdint>

#define BB 8
#define CC 512
#define DD 64
#define NN 16384
#define PARAM 10.0f
#define EPS 1e-6f

__device__ float g_Q[BB*DD*NN];     // phi(Q) [b][m][n]
__device__ float g_Kt[BB*NN*DD];    // phi(K) transposed [b][n][m]
__device__ float g_Ksum[BB*DD];
__device__ float g_KXT[BB*CC*DD];   // (phiK @ x^T)^T [b][c][m]
__device__ float g_KVT[BB*CC*DD];   // KV^T (no bias) [b][c][m]

__device__ __forceinline__ float fmap(float t) {
    return t > 0.f ? fmaf(PARAM, t, 1.f) : __expf(PARAM * t);
}
#define MMA8(d, a, b0, b1) \
    asm volatile("mma.sync.aligned.m16n8k8.row.col.f32.tf32.tf32.f32 " \
        "{%0,%1,%2,%3}, {%4,%5,%6,%7}, {%8,%9}, {%0,%1,%2,%3};" \
        : "+f"((d)[0]), "+f"((d)[1]), "+f"((d)[2]), "+f"((d)[3]) \
        : "r"((a)[0]), "r"((a)[1]), "r"((a)[2]), "r"((a)[3]), "r"(b0), "r"(b1))

// ---------------------------------------------------------------------------
__global__ void k_zero() {
    int i = blockIdx.x*blockDim.x + threadIdx.x;
    if (i < BB*CC*DD) { g_KXT[i] = 0.f; g_KVT[i] = 0.f; }
    if (i < BB*DD) g_Ksum[i] = 0.f;
}

// ---------------------------------------------------------------------------
// k_qk: [Wq;Wk](128x512) @ x_tile(512 x 128n). Raw-f32 tf32 MMA, double-
// buffered smem (1 sync/iter), vector STS. Epilogue: Q->g_Q, K->g_Kt + Ksum.
// ---------------------------------------------------------------------------
__global__ __launch_bounds__(256) void k_qk(const float* __restrict__ x,
        const float* __restrict__ Wq, const float* __restrict__ bq,
        const float* __restrict__ Wk, const float* __restrict__ bk) {
    extern __shared__ float S[];   // 2 stages x (As 128*36 + Bs 32*136)
    const int tid = threadIdx.x, w = tid>>5, lane = tid&31;
    const int gr = lane>>2, qt = lane&3;
    const int b = blockIdx.y, n0 = blockIdx.x*128;
    const int M0 = (w>>1)*32, N0 = (w&1)*64;
    const float* xb = x + (size_t)b*CC*NN;

    float4 pA[4], pB[4];
    #pragma unroll
    for (int i = 0; i < 4; i++) {
        int id = tid + i*256, r = id>>3, c4 = id&7;
        const float* Wr = r < 64 ? Wq + r*CC : Wk + (size_t)(r-64)*CC;
        pA[i] = *(const float4*)(Wr + c4*4);
    }
    #pragma unroll
    for (int i = 0; i < 4; i++) {
        int id = tid + i*256, r = id>>5, n4 = id&31;
        pB[i] = *(const float4*)(xb + (size_t)r*NN + n0 + n4*4);
    }
    float acc[2][8][4];
    #pragma unroll
    for (int mt = 0; mt < 2; mt++)
        #pragma unroll
        for (int nt = 0; nt < 8; nt++)
            #pragma unroll
            for (int i = 0; i < 4; i++) acc[mt][nt][i] = 0.f;

    for (int ci = 0; ci < 16; ci++) {
        float* As = S + (ci&1)*8960;
        float* Bs = As + 4608;
        #pragma unroll
        for (int i = 0; i < 4; i++) {
            int id = tid + i*256, r = id>>3, c4 = id&7;
            *(float4*)&As[r*36 + c4*4] = pA[i];
        }
        #pragma unroll
        for (int i = 0; i < 4; i++) {
            int id = tid + i*256, r = id>>5, n4 = id&31;
            *(float4*)&Bs[r*136 + n4*4] = pB[i];
        }
        __syncthreads();
        if (ci < 15) {
            int kc = (ci+1)*32;
            #pragma unroll
            for (int i = 0; i < 4; i++) {
                int id = tid + i*256, r = id>>3, c4 = id&7;
                const float* Wr = r < 64 ? Wq + r*CC : Wk + (size_t)(r-64)*CC;
                pA[i] = *(const float4*)(Wr + kc + c4*4);
            }
            #pragma unroll
            for (int i = 0; i < 4; i++) {
                int id = tid + i*256, r = id>>5, n4 = id&31;
                pB[i] = *(const float4*)(xb + (size_t)(kc+r)*NN + n0 + n4*4);
            }
        }
        #pragma unroll
        for (int k0 = 0; k0 < 32; k0 += 8) {
            uint32_t af[2][4], bf[8][2];
            #pragma unroll
            for (int mt = 0; mt < 2; mt++) {
                int base = (M0 + 16*mt + gr)*36 + k0 + qt;
                af[mt][0] = __float_as_uint(As[base]);
                af[mt][1] = __float_as_uint(As[base + 8*36]);
                af[mt][2] = __float_as_uint(As[base + 4]);
                af[mt][3] = __float_as_uint(As[base + 8*36 + 4]);
            }
            #pragma unroll
            for (int nt = 0; nt < 8; nt++) {
                int bb = (k0 + qt)*136 + N0 + 8*nt + gr;
                bf[nt][0] = __float_as_uint(Bs[bb]);
                bf[nt][1] = __float_as_uint(Bs[bb + 4*136]);
            }
            #pragma unroll
            for (int mt = 0; mt < 2; mt++)
                #pragma unroll
                for (int nt = 0; nt < 8; nt++)
                    MMA8(acc[mt][nt], af[mt], bf[nt][0], bf[nt][1]);
        }
    }

    #pragma unroll
    for (int mt = 0; mt < 2; mt++)
        #pragma unroll
        for (int h = 0; h < 2; h++) {
            const int m = M0 + 16*mt + 8*h + gr;
            const float bias = m < 64 ? __ldg(bq + m) : __ldg(bk + m - 64);
            float vv[8][2], ks = 0.f;
            #pragma unroll
            for (int nt = 0; nt < 8; nt++) {
                vv[nt][0] = fmap(acc[mt][nt][2*h]   + bias);
                vv[nt][1] = fmap(acc[mt][nt][2*h+1] + bias);
                ks += vv[nt][0] + vv[nt][1];
            }
            if (m < 64) {
                float* dst = g_Q + ((size_t)b*DD + m)*NN + n0 + N0;
                #pragma unroll
                for (int nt = 0; nt < 8; nt++)
                    *(float2*)(dst + 8*nt + 2*qt) = make_float2(vv[nt][0], vv[nt][1]);
            } else {
                const int mm = m - 64;
                #pragma unroll
                for (int nt = 0; nt < 8; nt++) {
                    int n = n0 + N0 + 8*nt + 2*qt;
                    float* dk = g_Kt + ((size_t)b*NN + n)*DD + mm;
                    dk[0] = vv[nt][0]; dk[DD] = vv[nt][1];
                }
                ks += __shfl_xor_sync(0xffffffffu, ks, 1);
                ks += __shfl_xor_sync(0xffffffffu, ks, 2);
                if (qt == 0) atomicAdd(&g_Ksum[b*DD + mm], ks);
            }
        }
}

// ---------------------------------------------------------------------------
// k_kx: KXT[128c][64m] += x_tile @ phiK^T. Raw-f32 tf32, double-buffered,
// vector STS (g_Kt rows already m-contiguous). Split-K=16, L2 atomics.
// ---------------------------------------------------------------------------
__global__ __launch_bounds__(256) void k_kx(const float* __restrict__ x) {
    extern __shared__ float S[];   // 2 stages x (As 128*36 + Bs 32*72)
    const int tid = threadIdx.x, w = tid>>5, lane = tid&31;
    const int gr = lane>>2, qt = lane&3;
    const int c0 = blockIdx.x*128, b = blockIdx.z;
    const int nbase = blockIdx.y*(NN/16);
    const int M0 = (w>>1)*32, N0 = (w&1)*32;

    float4 pA[4], pB[2];
    #pragma unroll
    for (int i = 0; i < 4; i++) {
        int id = tid + i*256, r = id>>3, n4 = id&7;
        pA[i] = *(const float4*)(x + ((size_t)(b*CC + c0 + r))*NN + nbase + n4*4);
    }
    #pragma unroll
    for (int i = 0; i < 2; i++) {
        int id = tid + i*256, r = id>>4, m4 = id&15;
        pB[i] = *(const float4*)(g_Kt + ((size_t)b*NN + nbase + r)*DD + m4*4);
    }
    float acc[2][4][4];
    #pragma unroll
    for (int mt = 0; mt < 2; mt++)
        #pragma unroll
        for (int nt = 0; nt < 4; nt++)
            #pragma unroll
            for (int i = 0; i < 4; i++) acc[mt][nt][i] = 0.f;

    for (int ci = 0; ci < (NN/16)/32; ci++) {
        float* As = S + (ci&1)*6912;
        float* Bs = As + 4608;
        #pragma unroll
        for (int i = 0; i < 4; i++) {
            int id = tid + i*256, r = id>>3, n4 = id&7;
            *(float4*)&As[r*36 + n4*4] = pA[i];
        }
        #pragma unroll
        for (int i = 0; i < 2; i++) {
            int id = tid + i*256, r = id>>4, m4 = id&15;
            *(float4*)&Bs[r*72 + m4*4] = pB[i];
        }
        __syncthreads();
        if (ci < (NN/16)/32 - 1) {
            int kn = nbase + (ci+1)*32;
            #pragma unroll
            for (int i = 0; i < 4; i++) {
                int id = tid + i*256, r = id>>3, n4 = id&7;
                pA[i] = *(const float4*)(x + ((size_t)(b*CC + c0 + r))*NN + kn + n4*4);
            }
            #pragma unroll
            for (int i = 0; i < 2; i++) {
                int id = tid + i*256, r = id>>4, m4 = id&15;
                pB[i] = *(const float4*)(g_Kt + ((size_t)b*NN + kn + r)*DD + m4*4);
            }
        }
        #pragma unroll
        for (int k0 = 0; k0 < 32; k0 += 8) {
            uint32_t af[2][4], bf[4][2];
            #pragma unroll
            for (int mt = 0; mt < 2; mt++) {
                int base = (M0 + 16*mt + gr)*36 + k0 + qt;
                af[mt][0] = __float_as_uint(As[base]);
                af[mt][1] = __float_as_uint(As[base + 8*36]);
                af[mt][2] = __float_as_uint(As[base + 4]);
                af[mt][3] = __float_as_uint(As[base + 8*36 + 4]);
            }
            #pragma unroll
            for (int nt = 0; nt < 4; nt++) {
                int bb = (k0 + qt)*72 + N0 + 8*nt + gr;
                bf[nt][0] = __float_as_uint(Bs[bb]);
                bf[nt][1] = __float_as_uint(Bs[bb + 4*72]);
            }
            #pragma unroll
            for (int mt = 0; mt < 2; mt++)
                #pragma unroll
                for (int nt = 0; nt < 4; nt++)
                    MMA8(acc[mt][nt], af[mt], bf[nt][0], bf[nt][1]);
        }
    }
    #pragma unroll
    for (int mt = 0; mt < 2; mt++)
        #pragma unroll
        for (int h = 0; h < 2; h++) {
            int c = c0 + M0 + 16*mt + 8*h + gr;
            #pragma unroll
            for (int nt = 0; nt < 4; nt++) {
                int m = N0 + 8*nt + 2*qt;
                float* d = g_KXT + ((size_t)b*CC + c)*DD + m;
                atomicAdd(d,     acc[mt][nt][2*h]);
                atomicAdd(d + 1, acc[mt][nt][2*h+1]);
            }
        }
}

// ---------------------------------------------------------------------------
// k_kv (SIMT, split-K=4): KVT[c][m] += sum_{c'} Wv[c][c'] * KXT[c'][m]
// ---------------------------------------------------------------------------
__global__ __launch_bounds__(256) void k_kv(const float* __restrict__ Wv) {
    __shared__ float Ws[64*36];
    __shared__ float Xs[32*68];
    const int c0 = blockIdx.x*64, sp = blockIdx.y, b = blockIdx.z;
    const int tid = threadIdx.x, tx = tid&15, ty = tid>>4;

    float acc[4][4] = {};
    for (int kk = 0; kk < 4; kk++) {
        const int cp0 = sp*128 + kk*32;
        #pragma unroll
        for (int i = 0; i < 2; i++) {
            int id = tid + i*256, r = id>>3, q4 = id&7;
            *(float4*)&Ws[r*36 + q4*4] =
                *(const float4*)(Wv + (size_t)(c0 + r)*CC + cp0 + q4*4);
        }
        #pragma unroll
        for (int i = 0; i < 2; i++) {
            int id = tid + i*256, r = id>>4, m4 = id&15;
            *(float4*)&Xs[r*68 + m4*4] =
                *(const float4*)(g_KXT + ((size_t)(b*CC) + cp0 + r)*DD + m4*4);
        }
        __syncthreads();
        #pragma unroll
        for (int k = 0; k < 32; k++) {
            float a[4], bb[4];
            #pragma unroll
            for (int i = 0; i < 4; i++) a[i] = Ws[(ty*4+i)*36 + k];
            #pragma unroll
            for (int j = 0; j < 4; j++) bb[j] = Xs[k*68 + tx*4 + j];
            #pragma unroll
            for (int i = 0; i < 4; i++)
                #pragma unroll
                for (int j = 0; j < 4; j++)
                    acc[i][j] = fmaf(a[i], bb[j], acc[i][j]);
        }
        __syncthreads();
    }
    #pragma unroll
    for (int i = 0; i < 4; i++)
        #pragma unroll
        for (int j = 0; j < 4; j++)
            atomicAdd(&g_KVT[((size_t)b*CC + c0 + ty*4+i)*DD + tx*4 + j], acc[i][j]);
}

// ---------------------------------------------------------------------------
// k_out: one block owns 64-n stripe; B=phiQ loaded once; A double-buffered
// across 8 c-chunks (1 sync/chunk). Raw-f32 tf32. Fused den + residual.
// ---------------------------------------------------------------------------
__global__ __launch_bounds__(256) void k_out(const float* __restrict__ x,
        const float* __restrict__ bv, const float* __restrict__ gamma,
        float* __restrict__ out) {
    extern __shared__ float S[];         // As[2][64*68] then Bs[64*72]
    float* Bs = S + 2*4352;
    __shared__ float dens[64], kss[64];
    const int tid = threadIdx.x, w = tid>>5, lane = tid&31;
    const int gr = lane>>2, qt = lane&3;
    const int n0 = blockIdx.x*64, b = blockIdx.y;
    const int M0 = (w>>1)*16, N0 = (w&1)*32;

    if (tid < 64) kss[tid] = g_Ksum[b*DD + tid];
    #pragma unroll
    for (int i = 0; i < 4; i++) {        // B = phiQ [m][n], loaded once
        int id = tid + i*256, r = id>>4, n4 = id&15;
        *(float4*)&Bs[r*72 + n4*4] =
            *(const float4*)(g_Q + ((size_t)b*DD + r)*NN + n0 + n4*4);
    }
    __syncthreads();
    if (tid < 64) {                      // den[n] = sum_m phiQ*(Ksum+eps)
        float d = 0.f;
        #pragma unroll 16
        for (int m = 0; m < 64; m++)
            d = fmaf(Bs[m*72 + tid], kss[m] + EPS, d);
        dens[tid] = d;
    }
    const float gm = gamma[0];

    float4 vA[4];
    #pragma unroll
    for (int i = 0; i < 4; i++) {        // prefetch chunk 0
        int id = tid + i*256, r = id>>4, m4 = id&15;
        vA[i] = *(const float4*)(g_KVT + ((size_t)b*CC + r)*DD + m4*4);
    }

    for (int cc = 0; cc < 8; cc++) {
        const int c0 = cc*64;
        float* As = S + (cc&1)*4352;
        #pragma unroll
        for (int i = 0; i < 4; i++) {    // A = KVT + bv*Ksum
            int id = tid + i*256, r = id>>4, m4 = id&15;
            float4 v = vA[i];
            float4 k4 = *(const float4*)(g_Ksum + b*DD + m4*4);
            float bvc = __ldg(bv + c0 + r);
            v.x = fmaf(bvc, k4.x, v.x); v.y = fmaf(bvc, k4.y, v.y);
            v.z = fmaf(bvc, k4.z, v.z); v.w = fmaf(bvc, k4.w, v.w);
            *(float4*)&As[r*68 + m4*4] = v;
        }
        __syncthreads();                 // As ready (covers dens on cc==0)
        if (cc < 7) {
            #pragma unroll
            for (int i = 0; i < 4; i++) {
                int id = tid + i*256, r = id>>4, m4 = id&15;
                vA[i] = *(const float4*)(g_KVT +
                        ((size_t)b*CC + c0 + 64 + r)*DD + m4*4);
            }
        }
        float acc[4][4];
        #pragma unroll
        for (int nt = 0; nt < 4; nt++)
            #pragma unroll
            for (int i = 0; i < 4; i++) acc[nt][i] = 0.f;
        #pragma unroll
        for (int k0 = 0; k0 < 64; k0 += 8) {
            uint32_t af[4], bf[4][2];
            int base = (M0 + gr)*68 + k0 + qt;
            af[0] = __float_as_uint(As[base]);
            af[1] = __float_as_uint(As[base + 8*68]);
            af[2] = __float_as_uint(As[base + 4]);
            af[3] = __float_as_uint(As[base + 8*68 + 4]);
            #pragma unroll
            for (int nt = 0; nt < 4; nt++) {
                int bb = (k0 + qt)*72 + N0 + 8*nt + gr;
                bf[nt][0] = __float_as_uint(Bs[bb]);
                bf[nt][1] = __float_as_uint(Bs[bb + 4*72]);
            }
            #pragma unroll
            for (int nt = 0; nt < 4; nt++)
                MMA8(acc[nt], af, bf[nt][0], bf[nt][1]);
        }
        #pragma unroll
        for (int h = 0; h < 2; h++) {
            const int c = c0 + M0 + 8*h + gr;
            #pragma unroll
            for (int nt = 0; nt < 4; nt++) {
                const int nl = N0 + 8*nt + 2*qt;
                const float rn0 = gm / dens[nl], rn1 = gm / dens[nl+1];
                const size_t bi = ((size_t)b*CC + c)*NN + n0 + nl;
                float2 xv = *(const float2*)(x + bi);
                float2 o;
                o.x = fmaf(acc[nt][2*h],   rn0, xv.x);
                o.y = fmaf(acc[nt][2*h+1], rn1, xv.y);
                *(float2*)(out + bi) = o;
            }
        }
    }
}

// ---------------------------------------------------------------------------
extern "C" void kernel_launch(void* const* d_in, const int* in_sizes, int n_in,
                              void* d_out, int out_size) {
    const float* x     = (const float*)d_in[0];
    const float* Wq    = (const float*)d_in[1];
    const float* bq    = (const float*)d_in[2];
    const float* Wk    = (const float*)d_in[3];
    const float* bk    = (const float*)d_in[4];
    const float* Wv    = (const float*)d_in[5];
    const float* bv    = (const float*)d_in[6];
    const float* gamma = (const float*)d_in[7];
    float* out = (float*)d_out;

    cudaFuncSetAttribute(k_qk,  cudaFuncAttributeMaxDynamicSharedMemorySize, 71680);
    cudaFuncSetAttribute(k_kx,  cudaFuncAttributeMaxDynamicSharedMemorySize, 55296);
    cudaFuncSetAttribute(k_out, cudaFuncAttributeMaxDynamicSharedMemorySize, 53248);

    k_zero<<<512, 512>>>();
    k_qk  <<<dim3(NN/128, BB), 256, 71680>>>(x, Wq, bq, Wk, bk);
    k_kx  <<<dim3(CC/128, 16, BB), 256, 55296>>>(x);
    k_kv  <<<dim3(CC/64, 4, BB), 256>>>(Wv);
    k_out <<<dim3(NN/64, BB), 256, 53248>>>(x, bv, gamma, out);
}